// round 4
// baseline (speedup 1.0000x reference)
#include <cuda_runtime.h>

typedef unsigned long long ULL;

#define Bn    8192
#define Hn    256
#define Pn    72
#define G3    768
#define INn   328
#define MLPn  256
#define BM    56
#define NTHR  256
#define SSTR  58
#define NBLK  147   // ceil(8192/56): 146 full CTAs + 1 with 16 rows

// ---------------- persistent device scratch (no allocations allowed) -------
__device__ float g_WihT[INn * G3];                    // [k][768]; k 0..255 text, 256..327 pose
__device__ float g_WhhT[Hn * G3];                     // [k][768]
__device__ float g_W1T [Hn * MLPn];                   // [k][256]
__device__ float g_W2T [MLPn * Pn];                   // [k][72]
__device__ float g_giT [(size_t)NBLK * G3 * BM];      // per-CTA blocked [cta][col][row]

// ---------------- f32x2 packed helpers (FFMA2 = 128 FMA/cyc/SM) ------------
static __device__ __forceinline__ ULL pack2(float lo, float hi) {
    ULL r; asm("mov.b64 %0, {%1, %2};" : "=l"(r) : "f"(lo), "f"(hi)); return r;
}
static __device__ __forceinline__ void unpack2(ULL v, float& lo, float& hi) {
    asm("mov.b64 {%0, %1}, %2;" : "=f"(lo), "=f"(hi) : "l"(v));
}
static __device__ __forceinline__ ULL fma2(ULL a, ULL b, ULL c) {
    ULL d; asm("fma.rn.f32x2 %0, %1, %2, %3;" : "=l"(d) : "l"(a), "l"(b), "l"(c)); return d;
}

static __device__ __forceinline__ float fsigmoid(float x) {
    x = fminf(fmaxf(x, -30.f), 30.f);
    return __fdividef(1.f, 1.f + __expf(-x));
}
static __device__ __forceinline__ float ftanh(float x) {
    x = fminf(fmaxf(x, -15.f), 15.f);
    float e = __expf(-2.f * x);
    return __fdividef(1.f - e, 1.f + e);
}

template<int NC>
static __device__ __forceinline__ void ldw(float (&w)[NC], const float* __restrict__ p) {
    if constexpr (NC == 4) {
        float4 v = *reinterpret_cast<const float4*>(p);
        w[0] = v.x; w[1] = v.y; w[2] = v.z; w[3] = v.w;
    } else {
        float2 v = *reinterpret_cast<const float2*>(p);
        w[0] = v.x; w[1] = v.y;
    }
}

// acc[JP][NC] (+=) A_T[k][rows] * W[k][cols].
// A_T: smem, k-major, row stride SSTR (rows are batch rows, 8B-aligned pairs).
// W: global, row stride WS, pre-offset to this thread's first column.
template<int K, int WS, int JP, int NC>
static __device__ __forceinline__ void gemm_acc(ULL (&acc)[JP][NC],
                                                const float* At, int r0,
                                                const float* __restrict__ W)
{
    float w0[NC], w1[NC], wn[NC];
    ldw<NC>(w0, W);
    ldw<NC>(w1, W + WS);
    #pragma unroll 4
    for (int k = 0; k < K; ++k) {
        const int kn = (k + 2 < K) ? (k + 2) : (K - 1);
        ldw<NC>(wn, W + (size_t)kn * WS);
        ULL wd[NC];
        #pragma unroll
        for (int c = 0; c < NC; ++c) wd[c] = pack2(w0[c], w0[c]);
        const ULL* hp = reinterpret_cast<const ULL*>(At + k * SSTR + r0);
        #pragma unroll
        for (int j = 0; j < JP; ++j) {
            ULL h2 = hp[j];
            #pragma unroll
            for (int c = 0; c < NC; ++c) acc[j][c] = fma2(h2, wd[c], acc[j][c]);
        }
        #pragma unroll
        for (int c = 0; c < NC; ++c) { w0[c] = w1[c]; w1[c] = wn[c]; }
    }
}

// ---------------- prep: transpose weights into k-major global scratch ------
__global__ __launch_bounds__(256)
void rtmg_prep(const float* __restrict__ W_ih, const float* __restrict__ W_hh,
               const float* __restrict__ W1,   const float* __restrict__ W2)
{
    const int idx = blockIdx.x * blockDim.x + threadIdx.x;
    const int stride = gridDim.x * blockDim.x;
    for (int i = idx; i < INn * G3;   i += stride) { int k = i / G3,   c = i % G3;   g_WihT[i] = W_ih[c * INn  + k]; }
    for (int i = idx; i < Hn * G3;    i += stride) { int k = i / G3,   c = i % G3;   g_WhhT[i] = W_hh[c * Hn   + k]; }
    for (int i = idx; i < Hn * MLPn;  i += stride) { int k = i / MLPn, c = i % MLPn; g_W1T[i]  = W1  [c * Hn   + k]; }
    for (int i = idx; i < MLPn * Pn;  i += stride) { int k = i / Pn,   c = i % Pn;   g_W2T[i]  = W2  [c * MLPn + k]; }
}

// ---------------- main persistent kernel ----------------------------------
__global__ __launch_bounds__(NTHR, 1)
void rtmg_main(const float* __restrict__ text,
               const float* __restrict__ prev0,
               const float* __restrict__ h0,
               const float* __restrict__ b_ih,
               const float* __restrict__ b_hh,
               const float* __restrict__ b1,
               const float* __restrict__ b2,
               float* __restrict__ out_poses,
               float* __restrict__ out_h,
               int steps)
{
    extern __shared__ float sm[];
    float* bufA  = sm;                     // h (initial)
    float* bufB  = bufA + Hn * SSTR;       // r gate / MLP hidden m
    float* bufC  = bufB + Hn * SSTR;       // text (init) / z gate / h_next
    float* sh_p  = bufC + Hn * SSTR;       // [72][SSTR] pose (k-major)
    float* sh_bh = sh_p + Pn * SSTR;       // b_hh [768]
    float* sh_b1 = sh_bh + G3;             // [256]
    float* sh_b2 = sh_b1 + MLPn;           // [72]

    const int tid     = threadIdx.x;
    const int rowbase = blockIdx.x * BM;
    const int nrows   = min(BM, Bn - rowbase);   // always even

    for (int i = tid; i < G3;   i += NTHR) sh_bh[i] = b_hh[i];
    for (int i = tid; i < MLPn; i += NTHR) sh_b1[i] = b1[i];
    for (int i = tid; i < Pn;   i += NTHR) sh_b2[i] = b2[i];

    // stage h (k-major) into bufA, text (k-major) into bufC; zero-pad
    for (int i = tid; i < Hn * BM; i += NTHR) {
        int r = i % BM, k = i / BM;
        float hv = 0.f, tv = 0.f;
        if (r < nrows) {
            size_t g = (size_t)(rowbase + r);
            hv = h0[g * Hn + k];
            tv = text[g * Hn + k];
        }
        bufA[k * SSTR + r] = hv;
        bufC[k * SSTR + r] = tv;
    }
    for (int i = tid; i < Pn * BM; i += NTHR) {
        int r = i % BM, k = i / BM;
        sh_p[k * SSTR + r] = (r < nrows) ? prev0[(size_t)(rowbase + r) * Pn + k] : 0.f;
    }
    __syncthreads();

    const int ct = tid & 63;          // 64 col-threads
    const int rt = tid >> 6;          // 4 row-threads
    const int r0 = rt * 14;           // 7 row-pairs each
    const int cc = ct * 4;            // 4 cols each (256-col passes)

    float* gi_blk = g_giT + (size_t)blockIdx.x * G3 * BM;

    // ---- precompute gi_base = text @ Wih_text^T + b_ih (+ b_hh for r,z) ----
    for (int g = 0; g < 3; ++g) {
        const int col = g * Hn + cc;
        ULL acc[7][4];
        #pragma unroll
        for (int c = 0; c < 4; ++c) {
            float bv = b_ih[col + c] + ((col + c < 512) ? b_hh[col + c] : 0.f);
            ULL bb = pack2(bv, bv);
            #pragma unroll
            for (int j = 0; j < 7; ++j) acc[j][c] = bb;
        }
        gemm_acc<Hn, G3, 7, 4>(acc, bufC, r0, g_WihT + col);
        #pragma unroll
        for (int c = 0; c < 4; ++c) {
            ULL* dst = reinterpret_cast<ULL*>(gi_blk + (size_t)(col + c) * BM + r0);
            #pragma unroll
            for (int j = 0; j < 7; ++j) dst[j] = acc[j][c];
        }
    }
    __syncthreads();   // bufC now free (reused as z / h_next)

    // MLP2 layout: 18 col-threads x 4 cols = 72; 14 row-threads x 4 rows
    const int  ct2  = tid % 18;
    const int  rt2  = tid / 18;
    const bool act2 = (rt2 < 14);
    const int  c0   = ct2 * 4;
    const int  r0b  = rt2 * 4;

    float* hbuf = bufA;
    float* zbuf = bufC;

    #pragma unroll 1
    for (int t = 0; t < steps; ++t) {
        // ---- pass 1: r and z gates (gi_base already has b_ih + b_hh) ----
        #pragma unroll 1
        for (int g = 0; g < 2; ++g) {
            const int col = g * Hn + cc;
            ULL acc[7][4];
            #pragma unroll
            for (int c = 0; c < 4; ++c) {
                const ULL* gp = reinterpret_cast<const ULL*>(gi_blk + (size_t)(col + c) * BM + r0);
                #pragma unroll
                for (int j = 0; j < 7; ++j) acc[j][c] = gp[j];
            }
            gemm_acc<Pn, G3, 7, 4>(acc, sh_p, r0, g_WihT + (size_t)Hn * G3 + col);
            gemm_acc<Hn, G3, 7, 4>(acc, hbuf, r0, g_WhhT + col);
            float* dst = (g == 0) ? bufB : zbuf;
            #pragma unroll
            for (int c = 0; c < 4; ++c)
                #pragma unroll
                for (int j = 0; j < 7; ++j) {
                    float lo, hi; unpack2(acc[j][c], lo, hi);
                    *reinterpret_cast<ULL*>(dst + (cc + c) * SSTR + r0 + 2 * j)
                        = pack2(fsigmoid(lo), fsigmoid(hi));
                }
        }
        __syncthreads();

        // ---- pass 2: n gate + h update; two column halves (reg pressure) ----
        #pragma unroll 1
        for (int half = 0; half < 2; ++half) {
            const int hc  = half * 128 + ct * 2;   // H-space column
            const int col = 512 + hc;              // gate column
            ULL gia[7][2], gha[7][2];
            #pragma unroll
            for (int c = 0; c < 2; ++c) {
                const ULL* gp = reinterpret_cast<const ULL*>(gi_blk + (size_t)(col + c) * BM + r0);
                float bv = sh_bh[col + c];
                ULL bb = pack2(bv, bv);
                #pragma unroll
                for (int j = 0; j < 7; ++j) { gia[j][c] = gp[j]; gha[j][c] = bb; }
            }
            gemm_acc<Pn, G3, 7, 2>(gia, sh_p, r0, g_WihT + (size_t)Hn * G3 + col);
            gemm_acc<Hn, G3, 7, 2>(gha, hbuf, r0, g_WhhT + col);
            #pragma unroll
            for (int c = 0; c < 2; ++c) {
                const int o = (hc + c) * SSTR + r0;
                #pragma unroll
                for (int j = 0; j < 7; ++j) {
                    float gil, gih, ghl, ghh, rl, rh, zl, zh, hl, hh;
                    unpack2(gia[j][c], gil, gih);
                    unpack2(gha[j][c], ghl, ghh);
                    unpack2(*reinterpret_cast<const ULL*>(bufB + o + 2 * j), rl, rh);
                    unpack2(*reinterpret_cast<const ULL*>(zbuf + o + 2 * j), zl, zh);
                    unpack2(*reinterpret_cast<const ULL*>(hbuf + o + 2 * j), hl, hh);
                    float nl = ftanh(gil + rl * ghl);
                    float nh = ftanh(gih + rh * ghh);
                    float ol = nl + zl * (hl - nl);   // (1-z)*n + z*h
                    float oh = nh + zh * (hh - nh);
                    *reinterpret_cast<ULL*>(zbuf + o + 2 * j) = pack2(ol, oh);
                }
            }
        }
        __syncthreads();
        { float* tb = hbuf; hbuf = zbuf; zbuf = tb; }   // h_next becomes h

        // ---- MLP layer 1: m = relu(h @ W1^T + b1) -> bufB ----
        {
            ULL acc[7][4];
            #pragma unroll
            for (int c = 0; c < 4; ++c) {
                float bv = sh_b1[cc + c];
                ULL bb = pack2(bv, bv);
                #pragma unroll
                for (int j = 0; j < 7; ++j) acc[j][c] = bb;
            }
            gemm_acc<Hn, MLPn, 7, 4>(acc, hbuf, r0, g_W1T + cc);
            #pragma unroll
            for (int c = 0; c < 4; ++c)
                #pragma unroll
                for (int j = 0; j < 7; ++j) {
                    float lo, hi; unpack2(acc[j][c], lo, hi);
                    *reinterpret_cast<ULL*>(bufB + (cc + c) * SSTR + r0 + 2 * j)
                        = pack2(fmaxf(lo, 0.f), fmaxf(hi, 0.f));
                }
        }
        __syncthreads();

        // ---- MLP layer 2: delta = m @ W2^T + b2; pose += delta; emit ----
        if (act2) {
            ULL acc[2][4];
            #pragma unroll
            for (int c = 0; c < 4; ++c) {
                float bv = sh_b2[c0 + c];
                ULL bb = pack2(bv, bv);
                acc[0][c] = bb; acc[1][c] = bb;
            }
            gemm_acc<MLPn, Pn, 2, 4>(acc, bufB, r0b, g_W2T + c0);
            #pragma unroll
            for (int j = 0; j < 2; ++j) {
                const int rr = r0b + 2 * j;
                float plo[4], phi[4];
                #pragma unroll
                for (int c = 0; c < 4; ++c) {
                    float dl, dh; unpack2(acc[j][c], dl, dh);
                    float* pp = sh_p + (c0 + c) * SSTR + rr;
                    float al = pp[0] + dl;
                    float ah = pp[1] + dh;
                    *reinterpret_cast<ULL*>(pp) = pack2(al, ah);
                    plo[c] = al; phi[c] = ah;
                }
                if (rr < nrows) {
                    const size_t grow = (size_t)(rowbase + rr);
                    *reinterpret_cast<float4*>(out_poses + (grow * steps + t) * Pn + c0)
                        = make_float4(plo[0], plo[1], plo[2], plo[3]);
                    *reinterpret_cast<float4*>(out_poses + ((grow + 1) * steps + t) * Pn + c0)
                        = make_float4(phi[0], phi[1], phi[2], phi[3]);
                }
            }
        }
        __syncthreads();
    }

    // ---- final hidden state ----
    if (out_h != nullptr) {
        for (int i = tid; i < Hn * BM; i += NTHR) {
            int r = i % BM, k = i / BM;
            if (r < nrows)
                out_h[(size_t)(rowbase + r) * Hn + k] = hbuf[k * SSTR + r];
        }
    }
}

// ---------------- launch ----------------------------------------------------
extern "C" void kernel_launch(void* const* d_in, const int* in_sizes, int n_in,
                              void* d_out, int out_size)
{
    const float* text  = (const float*)d_in[0];
    const float* prev0 = (const float*)d_in[1];
    const float* h0    = (const float*)d_in[2];
    // d_in[3] is the scalar `steps` if present; weights follow.
    const int wi = (n_in >= 12 && in_sizes[3] == 1) ? 4 : 3;
    const float* W_ih = (const float*)d_in[wi + 0];
    const float* W_hh = (const float*)d_in[wi + 1];
    const float* b_ih = (const float*)d_in[wi + 2];
    const float* b_hh = (const float*)d_in[wi + 3];
    const float* W1   = (const float*)d_in[wi + 4];
    const float* b1   = (const float*)d_in[wi + 5];
    const float* W2   = (const float*)d_in[wi + 6];
    const float* b2   = (const float*)d_in[wi + 7];

    // Derive steps from out_size (deterministic, host-side):
    //   tuple (poses, h_final): out_size = B*steps*72 + B*256  (not divisible by B*72)
    //   poses only            : out_size = B*steps*72
    long long os = (long long)out_size;
    const long long PB = (long long)Bn * Pn;       // 589824
    const long long HB = (long long)Bn * Hn;       // 2097152
    int steps;
    bool has_h;
    if (os % PB == 0) { steps = (int)(os / PB); has_h = false; }
    else              { steps = (int)((os - HB) / PB); has_h = true; }
    if (steps <= 0) { steps = 64; has_h = (os > (long long)Bn * 64 * Pn); }

    float* out_poses = (float*)d_out;
    float* out_h = has_h ? out_poses + (size_t)Bn * steps * Pn : nullptr;

    const size_t smem = (size_t)(3 * Hn * SSTR + Pn * SSTR + G3 + MLPn + Pn + 8) * sizeof(float);
    cudaFuncSetAttribute(rtmg_main, cudaFuncAttributeMaxDynamicSharedMemorySize, (int)smem);

    rtmg_prep<<<256, 256>>>(W_ih, W_hh, W1, W2);
    rtmg_main<<<NBLK, NTHR, smem>>>(text, prev0, h0, b_ih, b_hh, b1, b2,
                                    out_poses, out_h, steps);
}

// round 5
// speedup vs baseline: 1.0583x; 1.0583x over previous
#include <cuda_runtime.h>

typedef unsigned long long ULL;

#define Bn    8192
#define Hn    256
#define Pn    72
#define G3    768
#define INn   328
#define MLPn  256
#define BM    56
#define NTHR  512
#define SSTR  58
#define NBLK  147   // ceil(8192/56): 146 full CTAs + 1 with 16 rows

// ---------------- persistent device scratch (no allocations allowed) -------
// Weights stored transposed AND lane-duplicated: g[k][2c] = g[k][2c+1] = W[c][k]
// so an 8B/16B load yields ready f32x2 multiplier operands (no pack MOVs).
__device__ float g_WihT[INn * G3 * 2];                // [k][1536]
__device__ float g_WhhT[Hn * G3 * 2];                 // [k][1536]
__device__ float g_W1T [Hn * MLPn * 2];               // [k][512]
__device__ float g_W2T [MLPn * Pn * 2];               // [k][144]
__device__ float g_giT [(size_t)NBLK * G3 * BM];      // per-CTA blocked [cta][col][row]

// ---------------- f32x2 packed helpers (FFMA2 = 128 FMA/cyc/SM) ------------
static __device__ __forceinline__ ULL pack2(float lo, float hi) {
    ULL r; asm("mov.b64 %0, {%1, %2};" : "=l"(r) : "f"(lo), "f"(hi)); return r;
}
static __device__ __forceinline__ void unpack2(ULL v, float& lo, float& hi) {
    asm("mov.b64 {%0, %1}, %2;" : "=f"(lo), "=f"(hi) : "l"(v));
}
static __device__ __forceinline__ ULL fma2(ULL a, ULL b, ULL c) {
    ULL d; asm("fma.rn.f32x2 %0, %1, %2, %3;" : "=l"(d) : "l"(a), "l"(b), "l"(c)); return d;
}

static __device__ __forceinline__ float fsigmoid(float x) {
    x = fminf(fmaxf(x, -30.f), 30.f);
    return __fdividef(1.f, 1.f + __expf(-x));
}
static __device__ __forceinline__ float ftanh(float x) {
    x = fminf(fmaxf(x, -15.f), 15.f);
    float e = __expf(-2.f * x);
    return __fdividef(1.f - e, 1.f + e);
}

template<int NC>
static __device__ __forceinline__ void ldwd(ULL (&w)[NC], const float* __restrict__ p) {
    if constexpr (NC == 2) {
        ulonglong2 v = *reinterpret_cast<const ulonglong2*>(p);
        w[0] = v.x; w[1] = v.y;
    } else {
        w[0] = *reinterpret_cast<const ULL*>(p);
    }
}

// acc[JP][NC] += A_T[k][rows] * W[k][cols]  (W duplicated-lane layout)
// A_T: smem, k-major, row stride SSTR (8B-aligned row pairs, warp-broadcast).
// W: global, row stride WS floats, pre-offset to this thread's first dup column.
template<int K, int WS, int JP, int NC>
static __device__ __forceinline__ void gemm_acc(ULL (&acc)[JP][NC],
                                                const float* At, int r0,
                                                const float* __restrict__ W)
{
    ULL w0[NC], w1[NC];
    ldwd<NC>(w0, W);
    ldwd<NC>(w1, W + WS);
    #pragma unroll 4
    for (int k = 0; k < K; ++k) {
        const int kn = (k + 2 < K) ? (k + 2) : (K - 1);
        ULL wn[NC];
        ldwd<NC>(wn, W + (size_t)kn * WS);
        const ULL* hp = reinterpret_cast<const ULL*>(At + k * SSTR + r0);
        #pragma unroll
        for (int j = 0; j < JP; ++j) {
            ULL h2 = hp[j];
            #pragma unroll
            for (int c = 0; c < NC; ++c) acc[j][c] = fma2(h2, w0[c], acc[j][c]);
        }
        #pragma unroll
        for (int c = 0; c < NC; ++c) { w0[c] = w1[c]; w1[c] = wn[c]; }
    }
}

// ---------------- prep: transpose + duplicate weights -----------------------
__global__ __launch_bounds__(256)
void rtmg_prep(const float* __restrict__ W_ih, const float* __restrict__ W_hh,
               const float* __restrict__ W1,   const float* __restrict__ W2)
{
    const int idx = blockIdx.x * blockDim.x + threadIdx.x;
    const int stride = gridDim.x * blockDim.x;
    for (int i = idx; i < INn * G3; i += stride) {
        int k = i / G3, c = i % G3;
        float v = W_ih[c * INn + k];
        g_WihT[(size_t)k * (G3 * 2) + 2 * c]     = v;
        g_WihT[(size_t)k * (G3 * 2) + 2 * c + 1] = v;
    }
    for (int i = idx; i < Hn * G3; i += stride) {
        int k = i / G3, c = i % G3;
        float v = W_hh[c * Hn + k];
        g_WhhT[(size_t)k * (G3 * 2) + 2 * c]     = v;
        g_WhhT[(size_t)k * (G3 * 2) + 2 * c + 1] = v;
    }
    for (int i = idx; i < Hn * MLPn; i += stride) {
        int k = i / MLPn, c = i % MLPn;
        float v = W1[c * Hn + k];
        g_W1T[(size_t)k * (MLPn * 2) + 2 * c]     = v;
        g_W1T[(size_t)k * (MLPn * 2) + 2 * c + 1] = v;
    }
    for (int i = idx; i < MLPn * Pn; i += stride) {
        int k = i / Pn, c = i % Pn;
        float v = W2[c * MLPn + k];
        g_W2T[(size_t)k * (Pn * 2) + 2 * c]     = v;
        g_W2T[(size_t)k * (Pn * 2) + 2 * c + 1] = v;
    }
}

// ---------------- main persistent kernel -----------------------------------
__global__ __launch_bounds__(NTHR, 1)
void rtmg_main(const float* __restrict__ text,
               const float* __restrict__ prev0,
               const float* __restrict__ h0,
               const float* __restrict__ b_ih,
               const float* __restrict__ b_hh,
               const float* __restrict__ b1,
               const float* __restrict__ b2,
               float* __restrict__ out_poses,
               float* __restrict__ out_h,
               int steps)
{
    extern __shared__ float sm[];
    float* bufA  = sm;                     // h ping
    float* bufB  = bufA + Hn * SSTR;       // r gate / MLP hidden m
    float* bufC  = bufB + Hn * SSTR;       // text (init) / z gate / h pong
    float* sh_p  = bufC + Hn * SSTR;       // [72][SSTR] pose (k-major)
    float* sh_bh = sh_p + Pn * SSTR;       // b_hh [768]
    float* sh_b1 = sh_bh + G3;             // [256]
    float* sh_b2 = sh_b1 + MLPn;           // [72]

    const int tid     = threadIdx.x;
    const int rowbase = blockIdx.x * BM;
    const int nrows   = min(BM, Bn - rowbase);   // always even

    for (int i = tid; i < G3;   i += NTHR) sh_bh[i] = b_hh[i];
    for (int i = tid; i < MLPn; i += NTHR) sh_b1[i] = b1[i];
    for (int i = tid; i < Pn;   i += NTHR) sh_b2[i] = b2[i];

    // stage h (k-major) into bufA, text (k-major) into bufC; zero-pad
    for (int i = tid; i < Hn * BM; i += NTHR) {
        int r = i % BM, k = i / BM;
        float hv = 0.f, tv = 0.f;
        if (r < nrows) {
            size_t g = (size_t)(rowbase + r);
            hv = h0[g * Hn + k];
            tv = text[g * Hn + k];
        }
        bufA[k * SSTR + r] = hv;
        bufC[k * SSTR + r] = tv;
    }
    for (int i = tid; i < Pn * BM; i += NTHR) {
        int r = i % BM, k = i / BM;
        sh_p[k * SSTR + r] = (r < nrows) ? prev0[(size_t)(rowbase + r) * Pn + k] : 0.f;
    }
    __syncthreads();

    const int ct = tid & 127;         // 128 col-threads
    const int rt = tid >> 7;          // 4 row-threads
    const int r0 = rt * 14;           // 7 row-pairs each
    const int cc = ct * 2;            // 2 cols each (256-col passes)

    float* gi_blk = g_giT + (size_t)blockIdx.x * G3 * BM;

    // ---- precompute gi_base = text @ Wih_text^T + b_ih (+ b_hh for r,z) ----
    for (int g = 0; g < 3; ++g) {
        const int col = g * Hn + cc;
        ULL acc[7][2];
        #pragma unroll
        for (int c = 0; c < 2; ++c) {
            float bv = b_ih[col + c] + ((col + c < 512) ? b_hh[col + c] : 0.f);
            ULL bb = pack2(bv, bv);
            #pragma unroll
            for (int j = 0; j < 7; ++j) acc[j][c] = bb;
        }
        gemm_acc<Hn, G3 * 2, 7, 2>(acc, bufC, r0, g_WihT + 2 * col);
        #pragma unroll
        for (int c = 0; c < 2; ++c) {
            ULL* dst = reinterpret_cast<ULL*>(gi_blk + (size_t)(col + c) * BM + r0);
            #pragma unroll
            for (int j = 0; j < 7; ++j) dst[j] = acc[j][c];
        }
    }
    __syncthreads();   // bufC now free (reused as z / h pong)

    // MLP2 layout: 36 col-threads x 2 cols = 72; 14 row-threads x 4 rows
    const int  ct2  = tid % 36;
    const int  rt2  = tid / 36;
    const bool act2 = (rt2 < 14);
    const int  c0   = ct2 * 2;
    const int  r0b  = rt2 * 4;

    float* hbuf = bufA;
    float* zbuf = bufC;

    #pragma unroll 1
    for (int t = 0; t < steps; ++t) {
        // ---- pass 1: r and z gates (gi_base already has b_ih + b_hh) ----
        #pragma unroll 1
        for (int g = 0; g < 2; ++g) {
            const int col = g * Hn + cc;
            ULL acc[7][2];
            #pragma unroll
            for (int c = 0; c < 2; ++c) {
                const ULL* gp = reinterpret_cast<const ULL*>(gi_blk + (size_t)(col + c) * BM + r0);
                #pragma unroll
                for (int j = 0; j < 7; ++j) acc[j][c] = gp[j];
            }
            gemm_acc<Pn, G3 * 2, 7, 2>(acc, sh_p, r0, g_WihT + (size_t)Hn * (G3 * 2) + 2 * col);
            gemm_acc<Hn, G3 * 2, 7, 2>(acc, hbuf, r0, g_WhhT + 2 * col);
            float* dst = (g == 0) ? bufB : zbuf;
            #pragma unroll
            for (int c = 0; c < 2; ++c)
                #pragma unroll
                for (int j = 0; j < 7; ++j) {
                    float lo, hi; unpack2(acc[j][c], lo, hi);
                    *reinterpret_cast<ULL*>(dst + (cc + c) * SSTR + r0 + 2 * j)
                        = pack2(fsigmoid(lo), fsigmoid(hi));
                }
        }
        __syncthreads();

        // ---- pass 2: n gate + h update; 1 col/thread x 2 halves ----
        #pragma unroll 1
        for (int half = 0; half < 2; ++half) {
            const int hc  = half * 128 + ct;   // H-space column
            const int col = 512 + hc;          // gate column
            ULL gia[7][1], gha[7][1];
            {
                const ULL* gp = reinterpret_cast<const ULL*>(gi_blk + (size_t)col * BM + r0);
                float bv = sh_bh[col];
                ULL bb = pack2(bv, bv);
                #pragma unroll
                for (int j = 0; j < 7; ++j) { gia[j][0] = gp[j]; gha[j][0] = bb; }
            }
            gemm_acc<Pn, G3 * 2, 7, 1>(gia, sh_p, r0, g_WihT + (size_t)Hn * (G3 * 2) + 2 * col);
            gemm_acc<Hn, G3 * 2, 7, 1>(gha, hbuf, r0, g_WhhT + 2 * col);
            const int o = hc * SSTR + r0;
            #pragma unroll
            for (int j = 0; j < 7; ++j) {
                float gil, gih, ghl, ghh, rl, rh, zl, zh, hl, hh;
                unpack2(gia[j][0], gil, gih);
                unpack2(gha[j][0], ghl, ghh);
                unpack2(*reinterpret_cast<const ULL*>(bufB + o + 2 * j), rl, rh);
                unpack2(*reinterpret_cast<const ULL*>(zbuf + o + 2 * j), zl, zh);
                unpack2(*reinterpret_cast<const ULL*>(hbuf + o + 2 * j), hl, hh);
                float nl = ftanh(gil + rl * ghl);
                float nh = ftanh(gih + rh * ghh);
                float ol = nl + zl * (hl - nl);   // (1-z)*n + z*h
                float oh = nh + zh * (hh - nh);
                *reinterpret_cast<ULL*>(zbuf + o + 2 * j) = pack2(ol, oh);
            }
        }
        __syncthreads();
        { float* tb = hbuf; hbuf = zbuf; zbuf = tb; }   // h_next becomes h

        // ---- MLP layer 1: m = relu(h @ W1^T + b1) -> bufB ----
        {
            ULL acc[7][2];
            #pragma unroll
            for (int c = 0; c < 2; ++c) {
                float bv = sh_b1[cc + c];
                ULL bb = pack2(bv, bv);
                #pragma unroll
                for (int j = 0; j < 7; ++j) acc[j][c] = bb;
            }
            gemm_acc<Hn, MLPn * 2, 7, 2>(acc, hbuf, r0, g_W1T + 2 * cc);
            #pragma unroll
            for (int c = 0; c < 2; ++c)
                #pragma unroll
                for (int j = 0; j < 7; ++j) {
                    float lo, hi; unpack2(acc[j][c], lo, hi);
                    *reinterpret_cast<ULL*>(bufB + (cc + c) * SSTR + r0 + 2 * j)
                        = pack2(fmaxf(lo, 0.f), fmaxf(hi, 0.f));
                }
        }
        __syncthreads();

        // ---- MLP layer 2: delta = m @ W2^T + b2; pose += delta; emit ----
        if (act2) {
            ULL acc[2][2];
            #pragma unroll
            for (int c = 0; c < 2; ++c) {
                float bv = sh_b2[c0 + c];
                ULL bb = pack2(bv, bv);
                acc[0][c] = bb; acc[1][c] = bb;
            }
            gemm_acc<MLPn, Pn * 2, 2, 2>(acc, bufB, r0b, g_W2T + 2 * c0);
            #pragma unroll
            for (int j = 0; j < 2; ++j) {
                const int rr = r0b + 2 * j;
                float plo[2], phi[2];
                #pragma unroll
                for (int c = 0; c < 2; ++c) {
                    float dl, dh; unpack2(acc[j][c], dl, dh);
                    float* pp = sh_p + (c0 + c) * SSTR + rr;
                    float al = pp[0] + dl;
                    float ah = pp[1] + dh;
                    *reinterpret_cast<ULL*>(pp) = pack2(al, ah);
                    plo[c] = al; phi[c] = ah;
                }
                if (rr < nrows) {
                    const size_t grow = (size_t)(rowbase + rr);
                    *reinterpret_cast<ULL*>(out_poses + (grow * steps + t) * Pn + c0)
                        = pack2(plo[0], plo[1]);
                    *reinterpret_cast<ULL*>(out_poses + ((grow + 1) * steps + t) * Pn + c0)
                        = pack2(phi[0], phi[1]);
                }
            }
        }
        __syncthreads();
    }

    // ---- final hidden state ----
    if (out_h != nullptr) {
        for (int i = tid; i < Hn * BM; i += NTHR) {
            int r = i % BM, k = i / BM;
            if (r < nrows)
                out_h[(size_t)(rowbase + r) * Hn + k] = hbuf[k * SSTR + r];
        }
    }
}

// ---------------- launch -----------------------------------------------------
extern "C" void kernel_launch(void* const* d_in, const int* in_sizes, int n_in,
                              void* d_out, int out_size)
{
    const float* text  = (const float*)d_in[0];
    const float* prev0 = (const float*)d_in[1];
    const float* h0    = (const float*)d_in[2];
    const int wi = (n_in >= 12 && in_sizes[3] == 1) ? 4 : 3;
    const float* W_ih = (const float*)d_in[wi + 0];
    const float* W_hh = (const float*)d_in[wi + 1];
    const float* b_ih = (const float*)d_in[wi + 2];
    const float* b_hh = (const float*)d_in[wi + 3];
    const float* W1   = (const float*)d_in[wi + 4];
    const float* b1   = (const float*)d_in[wi + 5];
    const float* W2   = (const float*)d_in[wi + 6];
    const float* b2   = (const float*)d_in[wi + 7];

    // Derive steps from out_size (deterministic):
    //   tuple (poses, h_final): out_size = B*steps*72 + B*256
    //   poses only            : out_size = B*steps*72
    long long os = (long long)out_size;
    const long long PB = (long long)Bn * Pn;       // 589824
    const long long HB = (long long)Bn * Hn;       // 2097152
    int steps;
    bool has_h;
    if (os % PB == 0) { steps = (int)(os / PB); has_h = false; }
    else              { steps = (int)((os - HB) / PB); has_h = true; }
    if (steps <= 0) { steps = 64; has_h = (os > (long long)Bn * 64 * Pn); }

    float* out_poses = (float*)d_out;
    float* out_h = has_h ? out_poses + (size_t)Bn * steps * Pn : nullptr;

    const size_t smem = (size_t)(3 * Hn * SSTR + Pn * SSTR + G3 + MLPn + Pn + 8) * sizeof(float);
    cudaFuncSetAttribute(rtmg_main, cudaFuncAttributeMaxDynamicSharedMemorySize, (int)smem);

    rtmg_prep<<<256, 256>>>(W_ih, W_hh, W1, W2);
    rtmg_main<<<NBLK, NTHR, smem>>>(text, prev0, h0, b_ih, b_hh, b1, b2,
                                    out_poses, out_h, steps);
}

// round 6
// speedup vs baseline: 1.4347x; 1.3556x over previous
#include <cuda_runtime.h>

typedef unsigned long long ULL;

#define Bn    8192
#define Hn    256
#define Pn    72
#define G3    768
#define INn   328
#define MLPn  256
#define BM    64
#define NTHR  512
#define SSTR  68            // floats; 68*4=272B, 16B-aligned rows
#define NBLK  128           // 8192/64 exact

// ---------------- persistent device scratch (no allocations allowed) -------
// Transposed weights [k][outcol], +2 pad rows so 2-deep prefetch never faults.
__device__ float g_WihT[(INn + 2) * G3];
__device__ float g_WhhT[(Hn + 2) * G3];
__device__ float g_W1T [(Hn + 2) * MLPn];
__device__ float g_W2T [(MLPn + 2) * Pn];
__device__ float g_giT [(size_t)NBLK * G3 * BM];   // per-CTA [col][row] gi_text (+biases)

// ---------------- f32x2 packed helpers (FFMA2 = 128 FMA/cyc/SM) ------------
static __device__ __forceinline__ ULL pack2(float lo, float hi) {
    ULL r; asm("mov.b64 %0, {%1, %2};" : "=l"(r) : "f"(lo), "f"(hi)); return r;
}
static __device__ __forceinline__ void unpack2(ULL v, float& lo, float& hi) {
    asm("mov.b64 {%0, %1}, %2;" : "=f"(lo), "=f"(hi) : "l"(v));
}
static __device__ __forceinline__ ULL fma2(ULL a, ULL b, ULL c) {
    ULL d; asm("fma.rn.f32x2 %0, %1, %2, %3;" : "=l"(d) : "l"(a), "l"(b), "l"(c)); return d;
}

static __device__ __forceinline__ float fsigmoid(float x) {
    x = fminf(fmaxf(x, -30.f), 30.f);
    return __fdividef(1.f, 1.f + __expf(-x));
}
static __device__ __forceinline__ float ftanh(float x) {
    x = fminf(fmaxf(x, -15.f), 15.f);
    float e = __expf(-2.f * x);
    return __fdividef(1.f - e, 1.f + e);
}

// ---- dual-destination gemm: accA += At·W[:,cA..cA+1], accB += At·W[:,cB..cB+1]
// At: smem k-major, stride SSTR; rows r0..r0+7 (two 16B quads, warp-broadcast).
// WA/WB: global non-dup weights, row stride WS, pre-offset to the column pair.
template<int K, int WS>
static __device__ __forceinline__ void gemm_dual(
    ULL (&accA)[4][2], ULL (&accB)[4][2],
    const float* At, int r0,
    const float* __restrict__ WA, const float* __restrict__ WB)
{
    float2 a0 = *reinterpret_cast<const float2*>(WA);
    float2 a1 = *reinterpret_cast<const float2*>(WA + WS);
    float2 b0 = *reinterpret_cast<const float2*>(WB);
    float2 b1 = *reinterpret_cast<const float2*>(WB + WS);
    #pragma unroll 4
    for (int k = 0; k < K; ++k) {
        float2 a2 = *reinterpret_cast<const float2*>(WA + (size_t)(k + 2) * WS);
        float2 b2 = *reinterpret_cast<const float2*>(WB + (size_t)(k + 2) * WS);
        ulonglong2 h01 = *reinterpret_cast<const ulonglong2*>(At + k * SSTR + r0);
        ulonglong2 h23 = *reinterpret_cast<const ulonglong2*>(At + k * SSTR + r0 + 4);
        ULL wA0 = pack2(a0.x, a0.x), wA1 = pack2(a0.y, a0.y);
        ULL wB0 = pack2(b0.x, b0.x), wB1 = pack2(b0.y, b0.y);
        ULL h[4] = {h01.x, h01.y, h23.x, h23.y};
        #pragma unroll
        for (int j = 0; j < 4; ++j) {
            accA[j][0] = fma2(h[j], wA0, accA[j][0]);
            accA[j][1] = fma2(h[j], wA1, accA[j][1]);
            accB[j][0] = fma2(h[j], wB0, accB[j][0]);
            accB[j][1] = fma2(h[j], wB1, accB[j][1]);
        }
        a0 = a1; a1 = a2; b0 = b1; b1 = b2;
    }
}

// single-destination variant (MLP2)
template<int K, int WS>
static __device__ __forceinline__ void gemm_one(
    ULL (&acc)[4][2], const float* At, int r0, const float* __restrict__ W)
{
    float2 a0 = *reinterpret_cast<const float2*>(W);
    float2 a1 = *reinterpret_cast<const float2*>(W + WS);
    #pragma unroll 4
    for (int k = 0; k < K; ++k) {
        float2 a2 = *reinterpret_cast<const float2*>(W + (size_t)(k + 2) * WS);
        ulonglong2 h01 = *reinterpret_cast<const ulonglong2*>(At + k * SSTR + r0);
        ulonglong2 h23 = *reinterpret_cast<const ulonglong2*>(At + k * SSTR + r0 + 4);
        ULL w0 = pack2(a0.x, a0.x), w1 = pack2(a0.y, a0.y);
        ULL h[4] = {h01.x, h01.y, h23.x, h23.y};
        #pragma unroll
        for (int j = 0; j < 4; ++j) {
            acc[j][0] = fma2(h[j], w0, acc[j][0]);
            acc[j][1] = fma2(h[j], w1, acc[j][1]);
        }
        a0 = a1; a1 = a2;
    }
}

// ---------------- prep: transpose weights ----------------------------------
__global__ __launch_bounds__(256)
void rtmg_prep(const float* __restrict__ W_ih, const float* __restrict__ W_hh,
               const float* __restrict__ W1,   const float* __restrict__ W2)
{
    const int idx = blockIdx.x * blockDim.x + threadIdx.x;
    const int stride = gridDim.x * blockDim.x;
    for (int i = idx; i < INn * G3;  i += stride) { int k = i / G3,   c = i % G3;   g_WihT[(size_t)k * G3 + c]   = W_ih[c * INn  + k]; }
    for (int i = idx; i < Hn * G3;   i += stride) { int k = i / G3,   c = i % G3;   g_WhhT[(size_t)k * G3 + c]   = W_hh[c * Hn   + k]; }
    for (int i = idx; i < Hn * MLPn; i += stride) { int k = i / MLPn, c = i % MLPn; g_W1T[(size_t)k * MLPn + c]  = W1  [c * Hn   + k]; }
    for (int i = idx; i < MLPn * Pn; i += stride) { int k = i / Pn,   c = i % Pn;   g_W2T[(size_t)k * Pn + c]    = W2  [c * MLPn + k]; }
}

// ---------------- main persistent kernel -----------------------------------
__global__ __launch_bounds__(NTHR, 1)
void rtmg_main(const float* __restrict__ text,
               const float* __restrict__ prev0,
               const float* __restrict__ h0,
               const float* __restrict__ b_ih,
               const float* __restrict__ b_hh,
               const float* __restrict__ b1,
               const float* __restrict__ b2,
               float* __restrict__ out_poses,
               float* __restrict__ out_h,
               int steps)
{
    extern __shared__ float sm[];
    float* bufA   = sm;                    // h ping
    float* bufB   = bufA + Hn * SSTR;      // r / h pong
    float* bufC   = bufB + Hn * SSTR;      // text (init) / z / MLP hidden m
    float* sh_p   = bufC + Hn * SSTR;      // [72][SSTR] pose (k-major)
    float* sh_bhn = sh_p + Pn * SSTR;      // b_hh[512..767]  (n gate)
    float* sh_b1  = sh_bhn + 256;          // [256]
    float* sh_b2  = sh_b1 + MLPn;          // [72]

    const int tid     = threadIdx.x;
    const int rowbase = blockIdx.x * BM;

    for (int i = tid; i < 256;  i += NTHR) sh_bhn[i] = b_hh[512 + i];
    for (int i = tid; i < MLPn; i += NTHR) sh_b1[i] = b1[i];
    for (int i = tid; i < Pn;   i += NTHR) sh_b2[i] = b2[i];

    // stage h (k-major) into bufA, text into bufC, pose into sh_p (exact fit)
    for (int i = tid; i < Hn * BM; i += NTHR) {
        int r = i & 63, k = i >> 6;
        size_t g = (size_t)(rowbase + r);
        bufA[k * SSTR + r] = h0[g * Hn + k];
        bufC[k * SSTR + r] = text[g * Hn + k];
    }
    for (int i = tid; i < Pn * BM; i += NTHR) {
        int r = i & 63, k = i >> 6;
        sh_p[k * SSTR + r] = prev0[(size_t)(rowbase + r) * Pn + k];
    }
    __syncthreads();

    const int ct = tid & 63;          // 64 col-threads
    const int rt = tid >> 6;          // 8 row-threads
    const int r0 = rt * 8;            // 8 rows = 4 pairs = 2 quads (16B aligned)

    float* gi_blk = g_giT + (size_t)blockIdx.x * G3 * BM;
    const float* WihP = g_WihT + (size_t)Hn * G3;   // pose rows of W_ih

    // ---- precompute gi = text@WihT + b_ih (+ b_hh folded for r,z cols) ----
    #pragma unroll 1
    for (int g = 0; g < 3; ++g) {
        const int colA = g * 256 + (ct << 1);
        const int colB = colA + 128;
        ULL aA[4][2], aB[4][2];
        #pragma unroll
        for (int c = 0; c < 2; ++c) {
            float bA = b_ih[colA + c] + ((colA + c < 512) ? b_hh[colA + c] : 0.f);
            float bB = b_ih[colB + c] + ((colB + c < 512) ? b_hh[colB + c] : 0.f);
            ULL pA = pack2(bA, bA), pB = pack2(bB, bB);
            #pragma unroll
            for (int j = 0; j < 4; ++j) { aA[j][c] = pA; aB[j][c] = pB; }
        }
        gemm_dual<Hn, G3>(aA, aB, bufC, r0, g_WihT + colA, g_WihT + colB);
        #pragma unroll
        for (int c = 0; c < 2; ++c) {
            ULL* dA = reinterpret_cast<ULL*>(gi_blk + (size_t)(colA + c) * BM + r0);
            ULL* dB = reinterpret_cast<ULL*>(gi_blk + (size_t)(colB + c) * BM + r0);
            #pragma unroll
            for (int j = 0; j < 4; ++j) { dA[j] = aA[j][c]; dB[j] = aB[j][c]; }
        }
    }
    __syncthreads();   // bufC free

    // MLP2 layout: 36 col-threads x 2 cols; 8 row-threads x 8 rows
    const int  ct2  = tid % 36;
    const int  rt2  = tid / 36;
    const bool act2 = (rt2 < 8);
    const int  c0   = ct2 * 2;
    const int  r0b  = rt2 * 8;

    float* hbuf = bufA;
    float* rbuf = bufB;
    float* zbuf = bufC;

    #pragma unroll 1
    for (int t = 0; t < steps; ++t) {
        // ---- pass 1: r & z gates fused (gi holds b_ih + b_hh already) ----
        #pragma unroll 1
        for (int ch = 0; ch < 2; ++ch) {
            const int colR = ch * 128 + (ct << 1);   // 0..255 (H space)
            const int colZ = 256 + colR;
            ULL aR[4][2], aZ[4][2];
            #pragma unroll
            for (int c = 0; c < 2; ++c) {
                const ulonglong2* gR = reinterpret_cast<const ulonglong2*>(gi_blk + (size_t)(colR + c) * BM + r0);
                const ulonglong2* gZ = reinterpret_cast<const ulonglong2*>(gi_blk + (size_t)(colZ + c) * BM + r0);
                ulonglong2 x0 = gR[0], x1 = gR[1];
                aR[0][c] = x0.x; aR[1][c] = x0.y; aR[2][c] = x1.x; aR[3][c] = x1.y;
                ulonglong2 y0 = gZ[0], y1 = gZ[1];
                aZ[0][c] = y0.x; aZ[1][c] = y0.y; aZ[2][c] = y1.x; aZ[3][c] = y1.y;
            }
            gemm_dual<Pn, G3>(aR, aZ, sh_p, r0, WihP + colR, WihP + colZ);
            gemm_dual<Hn, G3>(aR, aZ, hbuf, r0, g_WhhT + colR, g_WhhT + colZ);
            #pragma unroll
            for (int c = 0; c < 2; ++c) {
                float v[8], w[8];
                #pragma unroll
                for (int j = 0; j < 4; ++j) {
                    unpack2(aR[j][c], v[2 * j], v[2 * j + 1]);
                    unpack2(aZ[j][c], w[2 * j], w[2 * j + 1]);
                }
                float* pr = rbuf + (colR + c) * SSTR + r0;
                float* pz = zbuf + (colR + c) * SSTR + r0;
                *reinterpret_cast<float4*>(pr)     = make_float4(fsigmoid(v[0]), fsigmoid(v[1]), fsigmoid(v[2]), fsigmoid(v[3]));
                *reinterpret_cast<float4*>(pr + 4) = make_float4(fsigmoid(v[4]), fsigmoid(v[5]), fsigmoid(v[6]), fsigmoid(v[7]));
                *reinterpret_cast<float4*>(pz)     = make_float4(fsigmoid(w[0]), fsigmoid(w[1]), fsigmoid(w[2]), fsigmoid(w[3]));
                *reinterpret_cast<float4*>(pz + 4) = make_float4(fsigmoid(w[4]), fsigmoid(w[5]), fsigmoid(w[6]), fsigmoid(w[7]));
            }
        }
        __syncthreads();

        // ---- pass 2: n gate (both halves fused) + h update ----
        {
            const int colA = (ct << 1);       // 0..127
            const int colB = colA + 128;      // 128..255
            ULL giA[4][2], giB[4][2], ghA[4][2], ghB[4][2];
            #pragma unroll
            for (int c = 0; c < 2; ++c) {
                const ulonglong2* gA = reinterpret_cast<const ulonglong2*>(gi_blk + (size_t)(512 + colA + c) * BM + r0);
                const ulonglong2* gB = reinterpret_cast<const ulonglong2*>(gi_blk + (size_t)(512 + colB + c) * BM + r0);
                ulonglong2 x0 = gA[0], x1 = gA[1];
                giA[0][c] = x0.x; giA[1][c] = x0.y; giA[2][c] = x1.x; giA[3][c] = x1.y;
                ulonglong2 y0 = gB[0], y1 = gB[1];
                giB[0][c] = y0.x; giB[1][c] = y0.y; giB[2][c] = y1.x; giB[3][c] = y1.y;
                float bA = sh_bhn[colA + c], bB = sh_bhn[colB + c];
                ULL pA = pack2(bA, bA), pB = pack2(bB, bB);
                #pragma unroll
                for (int j = 0; j < 4; ++j) { ghA[j][c] = pA; ghB[j][c] = pB; }
            }
            gemm_dual<Pn, G3>(giA, giB, sh_p, r0, WihP + 512 + colA, WihP + 512 + colB);
            gemm_dual<Hn, G3>(ghA, ghB, hbuf, r0, g_WhhT + 512 + colA, g_WhhT + 512 + colB);
            #pragma unroll
            for (int half = 0; half < 2; ++half) {
                const int base = half ? colB : colA;
                #pragma unroll
                for (int c = 0; c < 2; ++c) {
                    const int o = (base + c) * SSTR + r0;
                    const float4 rv0 = *reinterpret_cast<const float4*>(rbuf + o);
                    const float4 rv1 = *reinterpret_cast<const float4*>(rbuf + o + 4);
                    const float4 zv0 = *reinterpret_cast<const float4*>(zbuf + o);
                    const float4 zv1 = *reinterpret_cast<const float4*>(zbuf + o + 4);
                    const float4 hv0 = *reinterpret_cast<const float4*>(hbuf + o);
                    const float4 hv1 = *reinterpret_cast<const float4*>(hbuf + o + 4);
                    float rr[8] = {rv0.x, rv0.y, rv0.z, rv0.w, rv1.x, rv1.y, rv1.z, rv1.w};
                    float zz[8] = {zv0.x, zv0.y, zv0.z, zv0.w, zv1.x, zv1.y, zv1.z, zv1.w};
                    float hh[8] = {hv0.x, hv0.y, hv0.z, hv0.w, hv1.x, hv1.y, hv1.z, hv1.w};
                    float on[8];
                    #pragma unroll
                    for (int j = 0; j < 4; ++j) {
                        float gil, gih, ghl, ghh;
                        if (half) { unpack2(giB[j][c], gil, gih); unpack2(ghB[j][c], ghl, ghh); }
                        else      { unpack2(giA[j][c], gil, gih); unpack2(ghA[j][c], ghl, ghh); }
                        float nl = ftanh(gil + rr[2 * j]     * ghl);
                        float nh = ftanh(gih + rr[2 * j + 1] * ghh);
                        on[2 * j]     = nl + zz[2 * j]     * (hh[2 * j]     - nl);
                        on[2 * j + 1] = nh + zz[2 * j + 1] * (hh[2 * j + 1] - nh);
                    }
                    // h_next overwrites this thread's own r slots (element-wise)
                    *reinterpret_cast<float4*>(rbuf + o)     = make_float4(on[0], on[1], on[2], on[3]);
                    *reinterpret_cast<float4*>(rbuf + o + 4) = make_float4(on[4], on[5], on[6], on[7]);
                }
            }
        }
        __syncthreads();
        { float* tb = hbuf; hbuf = rbuf; rbuf = tb; }   // h_next -> hbuf

        // ---- MLP layer 1 (both halves fused): m = relu(h@W1T + b1) -> zbuf ----
        {
            const int colA = (ct << 1);
            const int colB = colA + 128;
            ULL aA[4][2], aB[4][2];
            #pragma unroll
            for (int c = 0; c < 2; ++c) {
                float bA = sh_b1[colA + c], bB = sh_b1[colB + c];
                ULL pA = pack2(bA, bA), pB = pack2(bB, bB);
                #pragma unroll
                for (int j = 0; j < 4; ++j) { aA[j][c] = pA; aB[j][c] = pB; }
            }
            gemm_dual<Hn, MLPn>(aA, aB, hbuf, r0, g_W1T + colA, g_W1T + colB);
            #pragma unroll
            for (int c = 0; c < 2; ++c) {
                float v[8], w[8];
                #pragma unroll
                for (int j = 0; j < 4; ++j) {
                    unpack2(aA[j][c], v[2 * j], v[2 * j + 1]);
                    unpack2(aB[j][c], w[2 * j], w[2 * j + 1]);
                }
                float* pA = zbuf + (colA + c) * SSTR + r0;
                float* pB = zbuf + (colB + c) * SSTR + r0;
                *reinterpret_cast<float4*>(pA)     = make_float4(fmaxf(v[0], 0.f), fmaxf(v[1], 0.f), fmaxf(v[2], 0.f), fmaxf(v[3], 0.f));
                *reinterpret_cast<float4*>(pA + 4) = make_float4(fmaxf(v[4], 0.f), fmaxf(v[5], 0.f), fmaxf(v[6], 0.f), fmaxf(v[7], 0.f));
                *reinterpret_cast<float4*>(pB)     = make_float4(fmaxf(w[0], 0.f), fmaxf(w[1], 0.f), fmaxf(w[2], 0.f), fmaxf(w[3], 0.f));
                *reinterpret_cast<float4*>(pB + 4) = make_float4(fmaxf(w[4], 0.f), fmaxf(w[5], 0.f), fmaxf(w[6], 0.f), fmaxf(w[7], 0.f));
            }
        }
        __syncthreads();

        // ---- MLP layer 2: delta = m@W2T + b2; pose += delta; emit ----
        if (act2) {
            ULL acc[4][2];
            #pragma unroll
            for (int c = 0; c < 2; ++c) {
                float bv = sh_b2[c0 + c];
                ULL bb = pack2(bv, bv);
                #pragma unroll
                for (int j = 0; j < 4; ++j) acc[j][c] = bb;
            }
            gemm_one<MLPn, Pn>(acc, zbuf, r0b, g_W2T + c0);
            #pragma unroll
            for (int j = 0; j < 4; ++j) {
                float d0l, d0h, d1l, d1h;
                unpack2(acc[j][0], d0l, d0h);
                unpack2(acc[j][1], d1l, d1h);
                float* p0 = sh_p + c0 * SSTR + r0b + 2 * j;
                float* p1 = sh_p + (c0 + 1) * SSTR + r0b + 2 * j;
                float a0l = p0[0] + d0l, a0h = p0[1] + d0h;
                float a1l = p1[0] + d1l, a1h = p1[1] + d1h;
                *reinterpret_cast<ULL*>(p0) = pack2(a0l, a0h);
                *reinterpret_cast<ULL*>(p1) = pack2(a1l, a1h);
                const size_t gr = (size_t)(rowbase + r0b + 2 * j);
                *reinterpret_cast<ULL*>(out_poses + (gr * steps + t) * Pn + c0)       = pack2(a0l, a1l);
                *reinterpret_cast<ULL*>(out_poses + ((gr + 1) * steps + t) * Pn + c0) = pack2(a0h, a1h);
            }
        }
        __syncthreads();
    }

    // ---- final hidden state ----
    if (out_h != nullptr) {
        for (int i = tid; i < Hn * BM; i += NTHR) {
            int r = i & 63, k = i >> 6;
            out_h[(size_t)(rowbase + r) * Hn + k] = hbuf[k * SSTR + r];
        }
    }
}

// ---------------- launch -----------------------------------------------------
extern "C" void kernel_launch(void* const* d_in, const int* in_sizes, int n_in,
                              void* d_out, int out_size)
{
    const float* text  = (const float*)d_in[0];
    const float* prev0 = (const float*)d_in[1];
    const float* h0    = (const float*)d_in[2];
    const int wi = (n_in >= 12 && in_sizes[3] == 1) ? 4 : 3;
    const float* W_ih = (const float*)d_in[wi + 0];
    const float* W_hh = (const float*)d_in[wi + 1];
    const float* b_ih = (const float*)d_in[wi + 2];
    const float* b_hh = (const float*)d_in[wi + 3];
    const float* W1   = (const float*)d_in[wi + 4];
    const float* b1   = (const float*)d_in[wi + 5];
    const float* W2   = (const float*)d_in[wi + 6];
    const float* b2   = (const float*)d_in[wi + 7];

    long long os = (long long)out_size;
    const long long PB = (long long)Bn * Pn;       // 589824
    const long long HB = (long long)Bn * Hn;       // 2097152
    int steps;
    bool has_h;
    if (os % PB == 0) { steps = (int)(os / PB); has_h = false; }
    else              { steps = (int)((os - HB) / PB); has_h = true; }
    if (steps <= 0) { steps = 64; has_h = (os > (long long)Bn * 64 * Pn); }

    float* out_poses = (float*)d_out;
    float* out_h = has_h ? out_poses + (size_t)Bn * steps * Pn : nullptr;

    const size_t smem = (size_t)(3 * Hn * SSTR + Pn * SSTR + 256 + MLPn + Pn) * sizeof(float);
    cudaFuncSetAttribute(rtmg_main, cudaFuncAttributeMaxDynamicSharedMemorySize, (int)smem);

    rtmg_prep<<<256, 256>>>(W_ih, W_hh, W1, W2);
    rtmg_main<<<NBLK, NTHR, smem>>>(text, prev0, h0, b_ih, b_hh, b1, b2,
                                    out_poses, out_h, steps);
}